// round 1
// baseline (speedup 1.0000x reference)
#include <cuda_runtime.h>

// Problem constants (match reference_code)
#define NN     512           // image H == W == N
#define NROWS  16            // channels C
#define NE     5             // elements
#define NL     12            // fluorescence lines
#define MB     (NROWS * NN)  // 8192 "rows" b = (c, h)

// out layout: fl_sig[NL][MB] followed by transmission[MB]

__global__ __launch_bounds__(512) void ppm_fused_kernel(
    const float* __restrict__ xp,        // (5, 16, 512, 512)
    const float* __restrict__ attCS,     // (5,)
    const float* __restrict__ dfu,       // (12,)
    const float* __restrict__ theta_p,   // (1,)
    const int*   __restrict__ lidx,      // (12,)
    float* __restrict__ out)
{
    const int b    = blockIdx.x;       // 0..8191  == c*512 + h
    const int c    = b >> 9;           // channel
    const int h    = b & (NN - 1);     // output row (H)
    const int w    = threadIdx.x;      // output col (W) == s
    const int lane = w & 31;
    const int wid  = w >> 5;           // 16 warps

    // --- rotation coordinates (exactly matching reference math) ---
    const float th = theta_p[0];
    float sn, cs;
    sincosf(th, &sn, &cs);

    const float inv = 1.0f / (float)NN;
    const float gx = (2.0f * (float)w + 1.0f) * inv - 1.0f;
    const float gy = (2.0f * (float)h + 1.0f) * inv - 1.0f;
    const float x_in = cs * gx - sn * gy;
    const float y_in = sn * gx + cs * gy;
    float ix = ((x_in + 1.0f) * (float)NN - 1.0f) * 0.5f;
    float iy = ((y_in + 1.0f) * (float)NN - 1.0f) * 0.5f;
    ix = fminf(fmaxf(ix, 0.0f), (float)(NN - 1));
    iy = fminf(fmaxf(iy, 0.0f), (float)(NN - 1));
    const float x0f = floorf(ix);
    const float y0f = floorf(iy);
    const float wx = ix - x0f;
    const float wy = iy - y0f;
    const int x0 = (int)x0f;
    const int y0 = (int)y0f;
    const int x1 = min(x0 + 1, NN - 1);
    const int y1 = min(y0 + 1, NN - 1);

    const float w00 = (1.0f - wx) * (1.0f - wy);
    const float w01 = wx * (1.0f - wy);
    const float w10 = (1.0f - wx) * wy;
    const float w11 = wx * wy;

    const int r0 = y0 << 9;
    const int r1 = y1 << 9;
    const float* base = xp + ((size_t)c << 18);  // c * 512*512

    // --- bilinear gather of 5 elements + lac dot product ---
    float conc[NE];
    float lac = 0.0f;
#pragma unroll
    for (int e = 0; e < NE; e++) {
        const float* img = base + ((size_t)e << 22);  // e * 16*512*512
        const float v = w00 * __ldg(img + r0 + x0)
                      + w01 * __ldg(img + r0 + x1)
                      + w10 * __ldg(img + r1 + x0)
                      + w11 * __ldg(img + r1 + x1);
        conc[e] = v;
        lac = fmaf(__ldg(attCS + e), v, lac);
    }

    // --- block-wide inclusive scan of lac over 512 threads ---
    float v = lac;
#pragma unroll
    for (int o = 1; o < 32; o <<= 1) {
        const float n = __shfl_up_sync(0xffffffffu, v, o);
        if (lane >= o) v += n;
    }
    __shared__ float wsum[16];
    __shared__ float woff[16];
    if (lane == 31) wsum[wid] = v;
    __syncthreads();
    if (wid == 0) {
        float x = (lane < 16) ? wsum[lane] : 0.0f;
#pragma unroll
        for (int o = 1; o < 16; o <<= 1) {
            const float n = __shfl_up_sync(0xffffffffu, x, o);
            if (lane >= o) x += n;
        }
        if (lane < 16) woff[lane] = x;
    }
    __syncthreads();

    const float incl = v + (wid ? woff[wid - 1] : 0.0f);
    const float scale = 0.01f / 512.0f;   // SAMPLE_SIZE_CM / N
    const float excl = incl - lac;        // exclusive prefix
    const float atten = expf(-excl * scale);

    // --- 5 block reductions of atten*conc[e] ---
    __shared__ float red[NE][16];
#pragma unroll
    for (int e = 0; e < NE; e++) {
        float s = atten * conc[e];
#pragma unroll
        for (int o = 16; o > 0; o >>= 1)
            s += __shfl_down_sync(0xffffffffu, s, o);
        if (lane == 0) red[e][wid] = s;
    }
    __syncthreads();

    __shared__ float Ssh[NE];
    if (w < NE) {
        float s = 0.0f;
#pragma unroll
        for (int k = 0; k < 16; k++) s += red[w][k];
        Ssh[w] = s;
    }
    __syncthreads();

    // --- outputs ---
    if (w < NL) {
        // K = PROBE_CTS * FL_RATIO * SA_ADJ * SA_THETA
        const float K = 100000.0f * 0.0017f;
        out[w * MB + b] = K * __ldg(dfu + w) * Ssh[__ldg(lidx + w)];
    }
    if (w == 0) {
        out[NL * MB + b] = woff[15] * scale;  // transmission = total cumsum * scale
    }
}

extern "C" void kernel_launch(void* const* d_in, const int* in_sizes, int n_in,
                              void* d_out, int out_size)
{
    const float* xp      = (const float*)d_in[0];
    const float* attCS   = (const float*)d_in[1];
    const float* dfu     = (const float*)d_in[2];
    const float* theta_p = (const float*)d_in[3];
    const int*   lidx    = (const int*)d_in[4];
    float* out = (float*)d_out;

    ppm_fused_kernel<<<MB, 512>>>(xp, attCS, dfu, theta_p, lidx, out);
}

// round 2
// speedup vs baseline: 1.5056x; 1.5056x over previous
#include <cuda_runtime.h>

// Problem constants (match reference_code)
#define NN     512           // image H == W == N
#define NE     5             // elements
#define NL     12            // fluorescence lines
#define MB     8192          // 16 channels * 512 rows
#define RPB    4             // output rows per block
#define STR    536           // smem row stride in floats: mult of 4 (float4), %32==24 (conflict-free)

// out layout: fl_sig[NL][MB] followed by transmission[MB]

__global__ __launch_bounds__(512, 2) void ppm_fused2_kernel(
    const float* __restrict__ xp,        // (5, 16, 512, 512)
    const float* __restrict__ attCS,     // (5,)
    const float* __restrict__ dfu,       // (12,)
    const float* __restrict__ theta_p,   // (1,)
    const int*   __restrict__ lidx,      // (12,)
    float* __restrict__ out)
{
    __shared__ float buf[RPB * STR];      // lac, later overwritten by atten
    __shared__ float warpTotS[16];
    __shared__ float warpOffS[16];
    __shared__ float rowTotS[RPB];
    __shared__ float partS[RPB][16][NE];
    __shared__ float Ssh[RPB][NE];

    const int tid    = threadIdx.x;
    const int lane   = tid & 31;
    const int warp   = tid >> 5;          // 0..15
    const int h_sub  = lane >> 3;         // 0..3 : row within block
    const int w_lane = lane & 7;          // 0..7 : w within warp patch

    const int b0 = blockIdx.x << 2;       // first of 4 rows (never straddles a channel: 512%4==0)
    const int b  = b0 + h_sub;
    const int c  = b >> 9;
    const int h  = b & (NN - 1);

    float sn, cs;
    sincosf(theta_p[0], &sn, &cs);
    const float inv = 1.0f / (float)NN;
    const float gy  = (2.0f * (float)h + 1.0f) * inv - 1.0f;

    const float* base = xp + ((size_t)c << 18);   // c * 512*512
    float a_e[NE];
#pragma unroll
    for (int e = 0; e < NE; e++) a_e[e] = __ldg(attCS + e);

    // ---------------- phase 1: gather (warp = 8w x 4h patch), 4 w-sweeps ----------------
    float conc[NE][4];
#pragma unroll
    for (int k = 0; k < 4; k++) {
        const int w = (k << 7) + (warp << 3) + w_lane;
        const float gx   = (2.0f * (float)w + 1.0f) * inv - 1.0f;
        const float x_in = cs * gx - sn * gy;
        const float y_in = sn * gx + cs * gy;
        float ix = ((x_in + 1.0f) * (float)NN - 1.0f) * 0.5f;
        float iy = ((y_in + 1.0f) * (float)NN - 1.0f) * 0.5f;
        ix = fminf(fmaxf(ix, 0.0f), (float)(NN - 1));
        iy = fminf(fmaxf(iy, 0.0f), (float)(NN - 1));
        const float x0f = floorf(ix);
        const float y0f = floorf(iy);
        const float wx = ix - x0f;
        const float wy = iy - y0f;
        const int x0 = (int)x0f;
        const int y0 = (int)y0f;
        const int x1 = min(x0 + 1, NN - 1);
        const int y1 = min(y0 + 1, NN - 1);
        const float w00 = (1.0f - wx) * (1.0f - wy);
        const float w01 = wx * (1.0f - wy);
        const float w10 = (1.0f - wx) * wy;
        const float w11 = wx * wy;
        const int r0 = y0 << 9;
        const int r1 = y1 << 9;

        float lac = 0.0f;
#pragma unroll
        for (int e = 0; e < NE; e++) {
            const float* img = base + ((size_t)e << 22);
            const float v = w00 * __ldg(img + r0 + x0)
                          + w01 * __ldg(img + r0 + x1)
                          + w10 * __ldg(img + r1 + x0)
                          + w11 * __ldg(img + r1 + x1);
            conc[e][k] = v;
            lac = fmaf(a_e[e], v, lac);
        }
        buf[h_sub * STR + w] = lac;
    }
    __syncthreads();

    // ---------------- phase 2: per-row 512-scan + exp (remapped: 128 thr/row, 4/thread) --
    const int row = tid >> 7;             // 0..3
    const int p   = tid & 127;            // chunk index within row
    const float4 v4 = *(const float4*)(buf + row * STR + (p << 2));
    const float c0 = v4.x;
    const float c1 = c0 + v4.y;
    const float c2 = c1 + v4.z;
    const float c3 = c2 + v4.w;
    const float tot = c3;

    // warp-inclusive scan of per-thread totals (each warp lies in one row)
    float sc = tot;
#pragma unroll
    for (int o = 1; o < 32; o <<= 1) {
        const float n = __shfl_up_sync(0xffffffffu, sc, o);
        if (lane >= o) sc += n;
    }
    if (lane == 31) warpTotS[warp] = sc;
    __syncthreads();

    if (warp == 0) {
        float val = (lane < 16) ? warpTotS[lane] : 0.0f;
        // inclusive scan within groups of 4 (warps of one row)
        float s = val;
        float n = __shfl_up_sync(0xffffffffu, s, 1, 4);
        if ((lane & 3) >= 1) s += n;
        n = __shfl_up_sync(0xffffffffu, s, 2, 4);
        if ((lane & 3) >= 2) s += n;
        if (lane < 16) {
            warpOffS[lane] = s - val;                 // exclusive offset
            if ((lane & 3) == 3) rowTotS[lane >> 2] = s;
        }
    }
    __syncthreads();

    const float scale = 0.01f / 512.0f;   // SAMPLE_SIZE_CM / N
    const float base_excl = warpOffS[warp] + (sc - tot);
    float4 at;
    at.x = expf(-base_excl * scale);
    at.y = expf(-(base_excl + c0) * scale);
    at.z = expf(-(base_excl + c1) * scale);
    at.w = expf(-(base_excl + c2) * scale);
    *(float4*)(buf + row * STR + (p << 2)) = at;      // own chunk only: safe
    __syncthreads();

    // ---------------- phase 3: fluorescence reduce (original mapping) --------------------
    float acc[NE] = {0.0f, 0.0f, 0.0f, 0.0f, 0.0f};
#pragma unroll
    for (int k = 0; k < 4; k++) {
        const int w = (k << 7) + (warp << 3) + w_lane;
        const float a = buf[h_sub * STR + w];
#pragma unroll
        for (int e = 0; e < NE; e++) acc[e] = fmaf(a, conc[e][k], acc[e]);
    }
#pragma unroll
    for (int e = 0; e < NE; e++) {
#pragma unroll
        for (int o = 4; o > 0; o >>= 1)
            acc[e] += __shfl_down_sync(0xffffffffu, acc[e], o, 8);
    }
    if (w_lane == 0) {
#pragma unroll
        for (int e = 0; e < NE; e++) partS[h_sub][warp][e] = acc[e];
    }
    __syncthreads();

    if (tid < RPB * NE) {
        const int r = tid / NE;
        const int e = tid - r * NE;
        float s = 0.0f;
#pragma unroll
        for (int k = 0; k < 16; k++) s += partS[r][k][e];
        Ssh[r][e] = s;
    }
    __syncthreads();

    // ---------------- outputs ------------------------------------------------------------
    if (tid < RPB * NL) {
        const int r = tid / NL;
        const int l = tid - r * NL;
        const float K = 100000.0f * 0.0017f;    // PROBE_CTS * FL_RATIO * SA_ADJ * SA_THETA
        out[l * MB + b0 + r] = K * __ldg(dfu + l) * Ssh[r][__ldg(lidx + l)];
    }
    if (tid >= 64 && tid < 64 + RPB) {
        const int r = tid - 64;
        out[NL * MB + b0 + r] = rowTotS[r] * scale;  // transmission
    }
}

extern "C" void kernel_launch(void* const* d_in, const int* in_sizes, int n_in,
                              void* d_out, int out_size)
{
    const float* xp      = (const float*)d_in[0];
    const float* attCS   = (const float*)d_in[1];
    const float* dfu     = (const float*)d_in[2];
    const float* theta_p = (const float*)d_in[3];
    const int*   lidx    = (const int*)d_in[4];
    float* out = (float*)d_out;

    ppm_fused2_kernel<<<MB / RPB, 512>>>(xp, attCS, dfu, theta_p, lidx, out);
}

// round 3
// speedup vs baseline: 1.5581x; 1.0349x over previous
#include <cuda_runtime.h>

// Problem constants
#define NN     512
#define NE     5
#define NL     12
#define MB     8192                 // 16 channels * 512 rows
#define SCALE  1.953125e-5f         // SAMPLE_SIZE_CM / N = 0.01/512
#define KFAC   170.0f               // PROBE_CTS * FL_RATIO * SA_ADJ * SA_THETA

// Pass-A tiling
#define TW     64                   // output tile width  (1 chunk)
#define TH     32                   // output tile height
#define NCHUNK 8                    // 512 / TW chunks per row
#define CW     75                   // smem bbox col capacity (stride)
#define CH     73                   // smem bbox row capacity
// worst case over theta: span = sqrt(63^2+31^2)+2 = 72.2 <= 73 <= 75. Always fits.

#define SMEM_BYTES (CH * CW * 20)   // float4 tile (e0..e3) + float tile (e4)

// scratch: per (row b, chunk): [T, S0..S4]
__device__ float g_scratch[MB * NCHUNK * 6];

// ───────────────────────────── Pass A: rotate + sample + chunk partials ─────
__global__ __launch_bounds__(512, 2) void ppm_passA(
    const float* __restrict__ xp,        // (5, 16, 512, 512)
    const float* __restrict__ attCS,     // (5,)
    const float* __restrict__ theta_p)   // (1,)
{
    extern __shared__ float4 dyn[];
    float4* sm4 = dyn;                          // [CH][CW] e0..e3
    float*  sm1 = (float*)(dyn + CH * CW);      // [CH][CW] e4

    const int tid  = threadIdx.x;
    const int lane = tid & 31;
    const int warp = tid >> 5;                  // 0..15

    const int bid = blockIdx.x;                 // 16c * 8tx * 16ty = 2048
    const int c   = bid >> 7;
    const int tx  = (bid >> 4) & 7;
    const int ty  = bid & 15;
    const int w0  = tx << 6;                    // tile origin
    const int h0  = ty << 5;

    float sn, cs;
    sincosf(theta_p[0], &sn, &cs);
    const float inv = 1.0f / (float)NN;

    // ---- bbox of source footprint from the 4 tile corners (affine => corners) ----
    float mnx = 1e30f, mxx = -1e30f, mny = 1e30f, mxy = -1e30f;
#pragma unroll
    for (int k = 0; k < 4; k++) {
        const int wv = w0 + ((k & 1) ? (TW - 1) : 0);
        const int hv = h0 + ((k & 2) ? (TH - 1) : 0);
        const float gx = (2.0f * (float)wv + 1.0f) * inv - 1.0f;
        const float gy = (2.0f * (float)hv + 1.0f) * inv - 1.0f;
        float ix = ((cs * gx - sn * gy + 1.0f) * (float)NN - 1.0f) * 0.5f;
        float iy = ((sn * gx + cs * gy + 1.0f) * (float)NN - 1.0f) * 0.5f;
        ix = fminf(fmaxf(ix, 0.0f), (float)(NN - 1));
        iy = fminf(fmaxf(iy, 0.0f), (float)(NN - 1));
        mnx = fminf(mnx, ix); mxx = fmaxf(mxx, ix);
        mny = fminf(mny, iy); mxy = fmaxf(mxy, iy);
    }
    const int xs0 = (int)floorf(mnx);
    const int ys0 = (int)floorf(mny);
    int bw = min((int)floorf(mxx) + 1, NN - 1) - xs0 + 1;
    int bh = min((int)floorf(mxy) + 1, NN - 1) - ys0 + 1;
    bw = min(bw, CW);
    bh = min(bh, CH);

    // ---- stage bbox for all 5 elements (coalesced LDG, STS.128 + STS.32) ----
    const float* __restrict__ pc = xp + ((size_t)c << 18);
    const int tot = bh * CW;
    for (int i = tid; i < tot; i += 512) {
        const int y = i / CW;
        const int x = i - y * CW;
        const int gys = min(ys0 + y, NN - 1);
        const int gxs = min(xs0 + x, NN - 1);     // cols >= bw load clamped dups (never sampled)
        const size_t off = ((size_t)gys << 9) + gxs;
        float4 v;
        v.x = __ldg(pc + off);
        v.y = __ldg(pc + (1u << 22) + off);
        v.z = __ldg(pc + (2u << 22) + off);
        v.w = __ldg(pc + (3u << 22) + off);
        sm4[i] = v;
        sm1[i] = __ldg(pc + ((size_t)4 << 22) + off);
    }

    const float a0 = __ldg(attCS + 0), a1 = __ldg(attCS + 1), a2 = __ldg(attCS + 2),
                a3 = __ldg(attCS + 3), a4 = __ldg(attCS + 4);
    __syncthreads();

    // ---- 2 sweeps: warp handles rows (warp) and (warp+16); lane covers 2 adjacent w ----
#pragma unroll
    for (int sweep = 0; sweep < 2; sweep++) {
        const int r = warp + (sweep << 4);        // 0..31
        const int h = h0 + r;
        const int b = (c << 9) + h;
        const float gy = (2.0f * (float)h + 1.0f) * inv - 1.0f;
        const float sgy = sn * gy, cgy = cs * gy;

        float conc[2][5];
        float lacv[2];
#pragma unroll
        for (int j = 0; j < 2; j++) {
            const int w = w0 + (lane << 1) + j;
            const float gx = (2.0f * (float)w + 1.0f) * inv - 1.0f;
            float ix = ((cs * gx - sgy + 1.0f) * (float)NN - 1.0f) * 0.5f;
            float iy = ((sn * gx + cgy + 1.0f) * (float)NN - 1.0f) * 0.5f;
            ix = fminf(fmaxf(ix, 0.0f), (float)(NN - 1));
            iy = fminf(fmaxf(iy, 0.0f), (float)(NN - 1));
            const float x0f = floorf(ix);
            const float y0f = floorf(iy);
            const float wx = ix - x0f;
            const float wy = iy - y0f;
            const int lx0 = (int)x0f - xs0;
            const int ly0 = (int)y0f - ys0;
            const int lx1 = min((int)x0f + 1, NN - 1) - xs0;
            const int ly1 = min((int)y0f + 1, NN - 1) - ys0;
            const float w00 = (1.0f - wx) * (1.0f - wy);
            const float w01 = wx * (1.0f - wy);
            const float w10 = (1.0f - wx) * wy;
            const float w11 = wx * wy;

            const int i00 = ly0 * CW + lx0;
            const int i01 = ly0 * CW + lx1;
            const int i10 = ly1 * CW + lx0;
            const int i11 = ly1 * CW + lx1;
            const float4 q00 = sm4[i00], q01 = sm4[i01], q10 = sm4[i10], q11 = sm4[i11];
            const float  e00 = sm1[i00], e01 = sm1[i01], e10 = sm1[i10], e11 = sm1[i11];

            conc[j][0] = w00 * q00.x + w01 * q01.x + w10 * q10.x + w11 * q11.x;
            conc[j][1] = w00 * q00.y + w01 * q01.y + w10 * q10.y + w11 * q11.y;
            conc[j][2] = w00 * q00.z + w01 * q01.z + w10 * q10.z + w11 * q11.z;
            conc[j][3] = w00 * q00.w + w01 * q01.w + w10 * q10.w + w11 * q11.w;
            conc[j][4] = w00 * e00   + w01 * e01   + w10 * e10   + w11 * e11;
            lacv[j] = a0 * conc[j][0] + a1 * conc[j][1] + a2 * conc[j][2]
                    + a3 * conc[j][3] + a4 * conc[j][4];
        }

        // warp inclusive scan of lane pair-sums -> local exclusive prefix within chunk
        const float pairsum = lacv[0] + lacv[1];
        float psc = pairsum;
#pragma unroll
        for (int o = 1; o < 32; o <<= 1) {
            const float n = __shfl_up_sync(0xffffffffu, psc, o);
            if (lane >= o) psc += n;
        }
        const float excl0 = psc - pairsum;
        const float at0 = __expf(-excl0 * SCALE);
        const float at1 = __expf(-(excl0 + lacv[0]) * SCALE);

        // locally attenuated per-element sums over the 64-wide chunk
        float S[NE];
#pragma unroll
        for (int e = 0; e < NE; e++) {
            float s = at0 * conc[0][e] + at1 * conc[1][e];
#pragma unroll
            for (int o = 16; o > 0; o >>= 1)
                s += __shfl_xor_sync(0xffffffffu, s, o);
            S[e] = s;                              // all lanes hold the sum
        }
        const float T = __shfl_sync(0xffffffffu, psc, 31);  // chunk lac total

        if (lane < 6) {
            float v = T;
            if (lane == 1) v = S[0];
            else if (lane == 2) v = S[1];
            else if (lane == 3) v = S[2];
            else if (lane == 4) v = S[3];
            else if (lane == 5) v = S[4];
            g_scratch[((size_t)(b << 3) + tx) * 6 + lane] = v;
        }
    }
}

// ───────────────────────────── Pass B: cross-chunk combine + outputs ────────
__global__ __launch_bounds__(256) void ppm_passB(
    const float* __restrict__ dfu,       // (12,)
    const int*   __restrict__ lidx,      // (12,)
    float* __restrict__ out)
{
    const int tid  = threadIdx.x;
    const int lane = tid & 31;
    const int warp = tid >> 5;
    const int b    = (blockIdx.x << 3) + warp;     // one row per warp

    float T = 0.0f, S0 = 0.0f, S1 = 0.0f, S2 = 0.0f, S3 = 0.0f, S4 = 0.0f;
    if (lane < NCHUNK) {
        const float* p = g_scratch + ((size_t)(b << 3) + lane) * 6;
        T  = p[0]; S0 = p[1]; S1 = p[2]; S2 = p[3]; S3 = p[4]; S4 = p[5];
    }
    // inclusive scan of T over 8 chunk-lanes
    float incl = T;
#pragma unroll
    for (int o = 1; o < 8; o <<= 1) {
        const float n = __shfl_up_sync(0xffffffffu, incl, o, 8);
        if ((lane & 7) >= o) incl += n;
    }
    const float wfac = __expf(-(incl - T) * SCALE);   // exp(-chunk prefix)
    float t0 = wfac * S0, t1 = wfac * S1, t2 = wfac * S2, t3 = wfac * S3, t4 = wfac * S4;
#pragma unroll
    for (int o = 4; o > 0; o >>= 1) {
        t0 += __shfl_xor_sync(0xffffffffu, t0, o, 8);
        t1 += __shfl_xor_sync(0xffffffffu, t1, o, 8);
        t2 += __shfl_xor_sync(0xffffffffu, t2, o, 8);
        t3 += __shfl_xor_sync(0xffffffffu, t3, o, 8);
        t4 += __shfl_xor_sync(0xffffffffu, t4, o, 8);
    }
    const float Ttot = __shfl_sync(0xffffffffu, incl, 7, 8);

    // lanes 0..7 of group 0 write up to 2 outputs each (13 values total)
    if (lane < 8) {
#pragma unroll
        for (int rep = 0; rep < 2; rep++) {
            const int idx = lane + (rep << 3);
            if (idx < NL) {
                const int e = __ldg(lidx + idx);
                float se = t0;
                if (e == 1) se = t1; else if (e == 2) se = t2;
                else if (e == 3) se = t3; else if (e == 4) se = t4;
                out[idx * MB + b] = KFAC * __ldg(dfu + idx) * se;
            } else if (idx == NL) {
                out[NL * MB + b] = Ttot * SCALE;   // transmission
            }
        }
    }
}

extern "C" void kernel_launch(void* const* d_in, const int* in_sizes, int n_in,
                              void* d_out, int out_size)
{
    const float* xp      = (const float*)d_in[0];
    const float* attCS   = (const float*)d_in[1];
    const float* dfu     = (const float*)d_in[2];
    const float* theta_p = (const float*)d_in[3];
    const int*   lidx    = (const int*)d_in[4];
    float* out = (float*)d_out;

    cudaFuncSetAttribute(ppm_passA, cudaFuncAttributeMaxDynamicSharedMemorySize, SMEM_BYTES);
    ppm_passA<<<2048, 512, SMEM_BYTES>>>(xp, attCS, theta_p);
    ppm_passB<<<MB / 8, 256>>>(dfu, lidx, out);
}